// round 2
// baseline (speedup 1.0000x reference)
#include <cuda_runtime.h>
#include <cstdint>

#define BB 32
#define NN 128
#define DD 64
#define HH 8

// intermediates (device globals — no allocation allowed)
__device__ float g_Q[BB*NN*DD];
__device__ float g_K[BB*NN*DD];
__device__ float g_V[BB*NN*DD];
__device__ float g_attn[BB*NN*DD];

__device__ __forceinline__ void fma2(unsigned long long &d, unsigned long long a, unsigned long long b){
    asm("fma.rn.f32x2 %0, %1, %2, %0;" : "+l"(d) : "l"(a), "l"(b));
}
__device__ __forceinline__ unsigned long long pack2(float lo, float hi){
    unsigned long long r;
    asm("mov.b64 %0, {%1, %2};" : "=l"(r) : "f"(lo), "f"(hi));
    return r;
}
__device__ __forceinline__ void unpack2(float &lo, float &hi, unsigned long long v){
    asm("mov.b64 {%0, %1}, %2;" : "=f"(lo), "=f"(hi) : "l"(v));
}

// ---------------------------------------------------------------------------
// Kernel 1: Q/K/V projections.  4 rows per 256-thread block.
// ---------------------------------------------------------------------------
__global__ __launch_bounds__(256) void qkv_kernel(
    const float* __restrict__ h,
    const float* __restrict__ Wq, const float* __restrict__ Wk, const float* __restrict__ Wv)
{
    __shared__ float sh[4][65];
    const int t = threadIdx.x, r = t >> 6, c = t & 63;
    const int row = blockIdx.x * 4 + r;
    sh[r][c] = h[row*64 + c];
    __syncthreads();
    float q = 0.f, k = 0.f, v = 0.f;
#pragma unroll 8
    for (int d = 0; d < 64; ++d){
        const float x = sh[r][d];
        q += x * Wq[d*64 + c];
        k += x * Wk[d*64 + c];
        v += x * Wv[d*64 + c];
    }
    g_Q[row*64 + c] = q;
    g_K[row*64 + c] = k * 0.35355339059327373f;   // DH^-0.5
    g_V[row*64 + c] = v;
}

// ---------------------------------------------------------------------------
// Kernel 2: main attention. One block per (i, b).
//   P = e[b,i,:,:] @ (We * Q_i)      [128 x 64]  -- f32x2 packed FMA
//   score[h,j] = sum_k P[j,h8+k] * K[b,j,h8+k]; exp/clip; * k_RW
//   attn[h,:] = sum_j s * V[b,j,h8:..] / max(sum_j s, 1e-6)
// Thread layout: 128 threads = hg(8 heads) x jg(16 j-groups); each thread owns
// j in {4jg..4jg+3} and {64+4jg..64+4jg+3}, hk in [8hg, 8hg+8).
// ---------------------------------------------------------------------------
__global__ __launch_bounds__(128, 4) void attn_kernel(
    const float* __restrict__ e,
    const float* __restrict__ We,
    const float* __restrict__ kRW)
{
    __shared__ __align__(16) float eT[32*132];   // half of e-tile, transposed+rotated
    __shared__ __align__(16) float Wp[64*64];    // We * Q_i
    __shared__ float sQ[64];
    __shared__ float sRW[128];
    __shared__ float red[16][8][10];

    const int t  = threadIdx.x;
    const int i  = blockIdx.x, b = blockIdx.y;
    const int jg = t & 15, hg = t >> 4;
    const int bi = b*NN + i;

    if (t < 64) sQ[t] = g_Q[bi*64 + t];
    sRW[t] = kRW[bi*128 + t];
    __syncthreads();

    // Wp[d][hk] = We[d][hk] * Q_i[hk]   (coalesced, conflict-free)
#pragma unroll
    for (int rep = 0; rep < 32; ++rep){
        const int idx = rep*128 + t;
        Wp[idx] = We[idx] * sQ[idx & 63];
    }

    unsigned long long acc[2][2][8];
#pragma unroll
    for (int g = 0; g < 2; ++g)
#pragma unroll
        for (int p = 0; p < 2; ++p)
#pragma unroll
            for (int kk = 0; kk < 8; ++kk) acc[g][p][kk] = 0ull;

    const float* eg = e + (size_t)bi * (NN*DD);

    for (int half = 0; half < 2; ++half){
        __syncthreads();
        // Load e[:, half*32 .. +32) transposed into eT with rotation:
        //   value e[j][dl] stored at eT[dl*132 + ((j + 4*(dl>>2)) & 127)]
        // Writer: conflict-free STS.32; reader: phase-optimal LDS.128.
#pragma unroll
        for (int it = 0; it < 8; ++it){
            const int f  = it*128 + t;
            const int j  = f >> 3;       // 0..127
            const int d4 = f & 7;        // 0..7 (d-quad within half)
            const float4 v = *reinterpret_cast<const float4*>(eg + j*64 + half*32 + d4*4);
            const int pj   = (j + 4*d4) & 127;
            const int base = (4*d4)*132;
            eT[base +       pj] = v.x;
            eT[base + 132 + pj] = v.y;
            eT[base + 264 + pj] = v.z;
            eT[base + 396 + pj] = v.w;
        }
        __syncthreads();

        const float* wrow = Wp + half*32*64 + hg*8;
#pragma unroll 4
        for (int dl = 0; dl < 32; ++dl){
            const int rot = dl >> 2;
            const int s0 = (jg + rot) & 31;
            const int s1 = (jg + 16 + rot) & 31;
            const ulonglong2 e0 = *reinterpret_cast<const ulonglong2*>(&eT[dl*132 + 4*s0]);
            const ulonglong2 e1 = *reinterpret_cast<const ulonglong2*>(&eT[dl*132 + 4*s1]);
            const float4 w0 = *reinterpret_cast<const float4*>(wrow + dl*64);
            const float4 w1 = *reinterpret_cast<const float4*>(wrow + dl*64 + 4);
            unsigned long long wd[8];
            wd[0] = pack2(w0.x, w0.x); wd[1] = pack2(w0.y, w0.y);
            wd[2] = pack2(w0.z, w0.z); wd[3] = pack2(w0.w, w0.w);
            wd[4] = pack2(w1.x, w1.x); wd[5] = pack2(w1.y, w1.y);
            wd[6] = pack2(w1.z, w1.z); wd[7] = pack2(w1.w, w1.w);
#pragma unroll
            for (int kk = 0; kk < 8; ++kk){
                fma2(acc[0][0][kk], e0.x, wd[kk]);
                fma2(acc[0][1][kk], e0.y, wd[kk]);
                fma2(acc[1][0][kk], e1.x, wd[kk]);
                fma2(acc[1][1][kk], e1.y, wd[kk]);
            }
        }
    }

    // unpack P[j][kk] (j pairs packed lo/hi)
    float P[2][4][8];
#pragma unroll
    for (int g = 0; g < 2; ++g)
#pragma unroll
        for (int p = 0; p < 2; ++p)
#pragma unroll
            for (int kk = 0; kk < 8; ++kk)
                unpack2(P[g][2*p][kk], P[g][2*p+1][kk], acc[g][p][kk]);

    float denom = 0.f;
    float vacc[8] = {0.f,0.f,0.f,0.f,0.f,0.f,0.f,0.f};
    const float* Kb = g_K + (size_t)b*NN*64 + hg*8;
    const float* Vb = g_V + (size_t)b*NN*64 + hg*8;
#pragma unroll
    for (int g = 0; g < 2; ++g){
#pragma unroll
        for (int jj = 0; jj < 4; ++jj){
            const int j = (g << 6) + 4*jg + jj;
            const float4 k0 = *reinterpret_cast<const float4*>(Kb + j*64);
            const float4 k1 = *reinterpret_cast<const float4*>(Kb + j*64 + 4);
            float sc = P[g][jj][0]*k0.x + P[g][jj][1]*k0.y + P[g][jj][2]*k0.z + P[g][jj][3]*k0.w
                     + P[g][jj][4]*k1.x + P[g][jj][5]*k1.y + P[g][jj][6]*k1.z + P[g][jj][7]*k1.w;
            sc = fminf(fmaxf(sc, -5.f), 5.f);
            const float s = __expf(sc) * sRW[j];
            denom += s;
            const float4 v0 = *reinterpret_cast<const float4*>(Vb + j*64);
            const float4 v1 = *reinterpret_cast<const float4*>(Vb + j*64 + 4);
            vacc[0] += s*v0.x; vacc[1] += s*v0.y; vacc[2] += s*v0.z; vacc[3] += s*v0.w;
            vacc[4] += s*v1.x; vacc[5] += s*v1.y; vacc[6] += s*v1.z; vacc[7] += s*v1.w;
        }
    }

#pragma unroll
    for (int kk = 0; kk < 8; ++kk) red[jg][hg][kk] = vacc[kk];
    red[jg][hg][8] = denom;
    __syncthreads();
    if (t < 64){
        const int hh = t >> 3, dd = t & 7;
        float s = 0.f, den = 0.f;
#pragma unroll
        for (int q = 0; q < 16; ++q){ s += red[q][hh][dd]; den += red[q][hh][8]; }
        den = fmaxf(den, 1e-6f);
        g_attn[bi*64 + hh*8 + dd] = s / den;
    }
}

// ---------------------------------------------------------------------------
// Kernel 3: O-projection + residual + LN1 + FFN + LN2.  4 rows / 256 threads.
// ---------------------------------------------------------------------------
__global__ __launch_bounds__(256) void tail_kernel(
    const float* __restrict__ h,
    const float* __restrict__ Wo, const float* __restrict__ bo,
    const float* __restrict__ g1, const float* __restrict__ b1g,
    const float* __restrict__ W1, const float* __restrict__ b1,
    const float* __restrict__ W2, const float* __restrict__ b2,
    const float* __restrict__ g2, const float* __restrict__ b2g,
    float* __restrict__ out)
{
    __shared__ float sa[4][65];
    __shared__ float sx[4][65];
    __shared__ float shd[4][130];
    const int t = threadIdx.x, r = t >> 6, c = t & 63;
    const int row = blockIdx.x * 4 + r;

    sa[r][c] = g_attn[row*64 + c];
    __syncthreads();
    float x = bo[c] + h[row*64 + c];
#pragma unroll 8
    for (int d = 0; d < 64; ++d) x += sa[r][d] * Wo[d*64 + c];

    // LN1
    sx[r][c] = x;
    __syncthreads();
    float m = 0.f;
#pragma unroll 8
    for (int d = 0; d < 64; ++d) m += sx[r][d];
    m *= (1.f/64.f);
    float v = 0.f;
#pragma unroll 8
    for (int d = 0; d < 64; ++d){ const float df = sx[r][d] - m; v += df*df; }
    v *= (1.f/64.f);
    const float h1 = (x - m) * rsqrtf(v + 1e-5f) * g1[c] + b1g[c];
    __syncthreads();
    sx[r][c] = h1;
    __syncthreads();

    // FFN up (2D = 128 hidden units; thread c owns units c and c+64)
    float a0 = b1[c], a1 = b1[c + 64];
#pragma unroll 8
    for (int d = 0; d < 64; ++d){
        const float xv = sx[r][d];
        a0 += xv * W1[d*128 + c];
        a1 += xv * W1[d*128 + c + 64];
    }
    shd[r][c]      = fmaxf(a0, 0.f);
    shd[r][c + 64] = fmaxf(a1, 0.f);
    __syncthreads();
    float ff = b2[c];
#pragma unroll 8
    for (int u = 0; u < 128; ++u) ff += shd[r][u] * W2[u*64 + c];
    const float x2 = h1 + ff;

    // LN2
    __syncthreads();
    sa[r][c] = x2;
    __syncthreads();
    float m2 = 0.f;
#pragma unroll 8
    for (int d = 0; d < 64; ++d) m2 += sa[r][d];
    m2 *= (1.f/64.f);
    float v2 = 0.f;
#pragma unroll 8
    for (int d = 0; d < 64; ++d){ const float df = sa[r][d] - m2; v2 += df*df; }
    v2 *= (1.f/64.f);
    out[row*64 + c] = (x2 - m2) * rsqrtf(v2 + 1e-5f) * g2[c] + b2g[c];
}

// ---------------------------------------------------------------------------
extern "C" void kernel_launch(void* const* d_in, const int* in_sizes, int n_in,
                              void* d_out, int out_size)
{
    (void)in_sizes; (void)n_in; (void)out_size;
    const float* h   = (const float*)d_in[0];
    // d_in[1] = p, unused by the reference
    const float* e   = (const float*)d_in[2];
    const float* kRW = (const float*)d_in[3];
    const float* Wq  = (const float*)d_in[4];
    const float* Wk  = (const float*)d_in[5];
    const float* We  = (const float*)d_in[6];
    const float* Wv  = (const float*)d_in[7];
    const float* Wo  = (const float*)d_in[8];
    const float* bo  = (const float*)d_in[9];
    const float* g1  = (const float*)d_in[10];
    const float* b1g = (const float*)d_in[11];
    const float* W1  = (const float*)d_in[12];
    const float* b1  = (const float*)d_in[13];
    const float* W2  = (const float*)d_in[14];
    const float* b2  = (const float*)d_in[15];
    const float* g2  = (const float*)d_in[16];
    const float* b2g = (const float*)d_in[17];
    float* out = (float*)d_out;

    qkv_kernel<<<BB*NN/4, 256>>>(h, Wq, Wk, Wv);
    dim3 grid(NN, BB);
    attn_kernel<<<grid, 128>>>(e, We, kRW);
    tail_kernel<<<BB*NN/4, 256>>>(h, Wo, bo, g1, b1g, W1, b1, W2, b2, g2, b2g, out);
}